// round 1
// baseline (speedup 1.0000x reference)
#include <cuda_runtime.h>
#include <math.h>

#define EMBED 1024
#define NHEAD 16
#define HD    64
#define BATCH 4
#define SEQ   2048
#define MTOT  (BATCH*SEQ)     // 8192
#define QKV_N (3*EMBED)       // 3072

// Scratch (device globals: no allocations allowed)
__device__ float g_Q[(size_t)BATCH*NHEAD*SEQ*HD];   // [bh][s][d], pre-scaled by 1/8
__device__ float g_K[(size_t)BATCH*NHEAD*SEQ*HD];
__device__ float g_V[(size_t)BATCH*NHEAD*SEQ*HD];
__device__ float g_AO[(size_t)BATCH*SEQ*EMBED];     // attention out, [b*s][h*64+d]

// ---------------------------------------------------------------------------
// SGEMM: C = A(MxK) @ W(NxK)^T  (K-major both), 64x64x16 tiles, 256 thr, 4x4
// ---------------------------------------------------------------------------
__global__ __launch_bounds__(256) void qkv_gemm_kernel(
    const float* __restrict__ A, const float* __restrict__ W,
    const float* __restrict__ bias)
{
    __shared__ __align__(16) float As[16][68];
    __shared__ __align__(16) float Bs[16][68];
    const int tid = threadIdx.x;
    const int tx = tid & 15, ty = tid >> 4;
    const int lr = tid >> 2, lc = tid & 3;
    const int m0 = blockIdx.y * 64, n0 = blockIdx.x * 64;
    const float4* A4 = (const float4*)A;
    const float4* W4 = (const float4*)W;

    float acc[4][4];
    #pragma unroll
    for (int i = 0; i < 4; i++)
        #pragma unroll
        for (int j = 0; j < 4; j++) acc[i][j] = 0.f;

    for (int k0 = 0; k0 < EMBED; k0 += 16) {
        float4 av = A4[(size_t)(m0 + lr) * (EMBED/4) + (k0 >> 2) + lc];
        float4 bv = W4[(size_t)(n0 + lr) * (EMBED/4) + (k0 >> 2) + lc];
        As[lc*4+0][lr] = av.x; As[lc*4+1][lr] = av.y;
        As[lc*4+2][lr] = av.z; As[lc*4+3][lr] = av.w;
        Bs[lc*4+0][lr] = bv.x; Bs[lc*4+1][lr] = bv.y;
        Bs[lc*4+2][lr] = bv.z; Bs[lc*4+3][lr] = bv.w;
        __syncthreads();
        #pragma unroll
        for (int kk = 0; kk < 16; kk++) {
            float4 a = *(const float4*)&As[kk][ty*4];
            float4 b = *(const float4*)&Bs[kk][tx*4];
            float ar[4] = {a.x, a.y, a.z, a.w};
            float br[4] = {b.x, b.y, b.z, b.w};
            #pragma unroll
            for (int i = 0; i < 4; i++)
                #pragma unroll
                for (int j = 0; j < 4; j++) acc[i][j] += ar[i] * br[j];
        }
        __syncthreads();
    }

    // Epilogue: bias + head split. Reference reshapes [3E] -> [H, 3*hd]:
    // n -> h = n/192, r = n%192; r<64: Q(d=r), r<128: K(d=r-64), else V(d=r-128)
    #pragma unroll
    for (int j = 0; j < 4; j++) {
        int n = n0 + tx*4 + j;
        int h = n / 192;
        int r = n - h * 192;
        int w = r >> 6;
        int d = r & 63;
        float bsv = bias[n];
        #pragma unroll
        for (int i = 0; i < 4; i++) {
            int m = m0 + ty*4 + i;
            int b = m >> 11, s = m & (SEQ - 1);
            size_t idx = (((size_t)(b * NHEAD + h)) * SEQ + s) * HD + d;
            float v = acc[i][j] + bsv;
            if (w == 0)      g_Q[idx] = v * 0.125f;   // 1/sqrt(64)
            else if (w == 1) g_K[idx] = v;
            else             g_V[idx] = v;
        }
    }
}

__global__ __launch_bounds__(256) void proj_gemm_kernel(
    const float* __restrict__ W, const float* __restrict__ bias,
    float* __restrict__ C)
{
    __shared__ __align__(16) float As[16][68];
    __shared__ __align__(16) float Bs[16][68];
    const int tid = threadIdx.x;
    const int tx = tid & 15, ty = tid >> 4;
    const int lr = tid >> 2, lc = tid & 3;
    const int m0 = blockIdx.y * 64, n0 = blockIdx.x * 64;
    const float4* A4 = (const float4*)g_AO;
    const float4* W4 = (const float4*)W;

    float acc[4][4];
    #pragma unroll
    for (int i = 0; i < 4; i++)
        #pragma unroll
        for (int j = 0; j < 4; j++) acc[i][j] = 0.f;

    for (int k0 = 0; k0 < EMBED; k0 += 16) {
        float4 av = A4[(size_t)(m0 + lr) * (EMBED/4) + (k0 >> 2) + lc];
        float4 bv = W4[(size_t)(n0 + lr) * (EMBED/4) + (k0 >> 2) + lc];
        As[lc*4+0][lr] = av.x; As[lc*4+1][lr] = av.y;
        As[lc*4+2][lr] = av.z; As[lc*4+3][lr] = av.w;
        Bs[lc*4+0][lr] = bv.x; Bs[lc*4+1][lr] = bv.y;
        Bs[lc*4+2][lr] = bv.z; Bs[lc*4+3][lr] = bv.w;
        __syncthreads();
        #pragma unroll
        for (int kk = 0; kk < 16; kk++) {
            float4 a = *(const float4*)&As[kk][ty*4];
            float4 b = *(const float4*)&Bs[kk][tx*4];
            float ar[4] = {a.x, a.y, a.z, a.w};
            float br[4] = {b.x, b.y, b.z, b.w};
            #pragma unroll
            for (int i = 0; i < 4; i++)
                #pragma unroll
                for (int j = 0; j < 4; j++) acc[i][j] += ar[i] * br[j];
        }
        __syncthreads();
    }

    float4 bb = *(const float4*)&bias[n0 + tx*4];
    float br4[4] = {bb.x, bb.y, bb.z, bb.w};
    #pragma unroll
    for (int i = 0; i < 4; i++) {
        int m = m0 + ty*4 + i;
        float4 o;
        o.x = acc[i][0] + br4[0];
        o.y = acc[i][1] + br4[1];
        o.z = acc[i][2] + br4[2];
        o.w = acc[i][3] + br4[3];
        *(float4*)&C[(size_t)m * EMBED + n0 + tx*4] = o;
    }
}

// ---------------------------------------------------------------------------
// Flash attention fp32. Block: 128 queries x one (b,h); 256 threads.
// Thread = (query q, d-half). Online softmax; probs staged via smem Ps.
// Smem skew (+ (idx>>5)) on stride-66 rows avoids the 2-way conflicts that
// any plain stride gives between rows/columns 32 apart.
// ---------------------------------------------------------------------------
#define BM 128
#define BN 64
#define QS_STRIDE 65
#define KS_STRIDE 66
#define PS_STRIDE 66
#define QS_SZ (BM*QS_STRIDE)          // 8320
#define KS_SZ (BN*KS_STRIDE + 2)      // 4226
#define VS_SZ (BN*KS_STRIDE + 2)      // 4226
#define PS_SZ (BM*PS_STRIDE + 2)      // 8450
#define ATT_SMEM_FLOATS (QS_SZ + KS_SZ + VS_SZ + PS_SZ)
#define ATT_SMEM_BYTES  (ATT_SMEM_FLOATS * 4)   // 100,888 B -> 2 blocks/SM

__global__ __launch_bounds__(256) void attn_kernel()
{
    extern __shared__ float smbuf[];
    float* Qs = smbuf;
    float* Ks = Qs + QS_SZ;
    float* Vs = Ks + KS_SZ;
    float* Ps = Vs + VS_SZ;

    const int tid  = threadIdx.x;
    const int q    = tid >> 1;
    const int half = tid & 1;
    const int bh   = blockIdx.y;
    const int q0   = blockIdx.x * BM;

    // Load Q tile [128][64] (pre-scaled)
    const float4* Qg = (const float4*)(g_Q + ((size_t)bh * SEQ + q0) * HD);
    #pragma unroll
    for (int i = 0; i < 8; i++) {
        int idx = i * 256 + tid;
        int r = idx >> 4, c4 = idx & 15;
        float4 v = Qg[idx];
        float* dst = &Qs[r * QS_STRIDE + c4 * 4];
        dst[0] = v.x; dst[1] = v.y; dst[2] = v.z; dst[3] = v.w;
    }

    const float4* Kg = (const float4*)(g_K + (size_t)bh * SEQ * HD);
    const float4* Vg = (const float4*)(g_V + (size_t)bh * SEQ * HD);

    float mrun = -INFINITY, lrun = 0.f;
    float o[32];
    #pragma unroll
    for (int dd = 0; dd < 32; dd++) o[dd] = 0.f;

    const float* qrow = &Qs[q * QS_STRIDE];
    const float* kb   = Ks + (half * 32) * KS_STRIDE + half;  // row skew (j>>5)==half
    const float* vb   = Vs + half * 33;                       // col skew (d>>5)==half
    float*       prow = &Ps[q * PS_STRIDE];
    const int jbase   = half * 32;

    for (int t = 0; t < SEQ / BN; t++) {
        __syncthreads();   // prior iteration's Ks/Vs reads done before overwrite
        #pragma unroll
        for (int i = 0; i < 4; i++) {
            int idx = i * 256 + tid;
            int r = idx >> 4, c4 = idx & 15, db = c4 * 4;
            float4 kv = Kg[(size_t)(t * BN) * 16 + idx];
            float4 vv = Vg[(size_t)(t * BN) * 16 + idx];
            float* kd = &Ks[r * KS_STRIDE + (r >> 5) + db];
            kd[0] = kv.x; kd[1] = kv.y; kd[2] = kv.z; kd[3] = kv.w;
            float* vd = &Vs[r * KS_STRIDE + db + (db >> 5)];
            vd[0] = vv.x; vd[1] = vv.y; vd[2] = vv.z; vd[3] = vv.w;
        }
        __syncthreads();

        // Scores: 32 j's per thread over full d=64
        float p[32];
        #pragma unroll
        for (int jj = 0; jj < 32; jj++) p[jj] = 0.f;
        #pragma unroll 4
        for (int d = 0; d < HD; d++) {
            float qv = qrow[d];
            #pragma unroll
            for (int jj = 0; jj < 32; jj++)
                p[jj] += qv * kb[jj * KS_STRIDE + d];
        }

        // Online softmax (pairwise over the two d/j halves via shfl)
        float mx = p[0];
        #pragma unroll
        for (int jj = 1; jj < 32; jj++) mx = fmaxf(mx, p[jj]);
        mx = fmaxf(mx, __shfl_xor_sync(0xffffffffu, mx, 1));
        float mnew = fmaxf(mrun, mx);
        float corr = __expf(mrun - mnew);
        float ls = 0.f;
        #pragma unroll
        for (int jj = 0; jj < 32; jj++) {
            p[jj] = __expf(p[jj] - mnew);
            ls += p[jj];
        }
        ls += __shfl_xor_sync(0xffffffffu, ls, 1);
        lrun = lrun * corr + ls;
        mrun = mnew;
        #pragma unroll
        for (int dd = 0; dd < 32; dd++) o[dd] *= corr;

        // Stage probs to smem (warp-local exchange between halves)
        #pragma unroll
        for (int jj = 0; jj < 32; jj++) prow[jbase + jj + half] = p[jj];
        __syncwarp();

        // PV: O[d-half] += P[q][j] * V[j][d-half], all 64 j
        for (int j = 0; j < BN; j++) {
            float pj = prow[j + (j >> 5)];
            const float* vr = vb + j * KS_STRIDE;
            #pragma unroll
            for (int dd = 0; dd < 32; dd++) o[dd] += pj * vr[dd];
        }
        __syncwarp();  // partner may not overwrite prow before our reads finish
    }

    float inv = 1.f / lrun;
    int b = bh >> 4, h = bh & 15;
    float* dst = g_AO + ((size_t)(b * SEQ + q0 + q)) * EMBED + h * HD + half * 32;
    #pragma unroll
    for (int dd = 0; dd < 32; dd += 4) {
        float4 w4 = make_float4(o[dd] * inv, o[dd+1] * inv, o[dd+2] * inv, o[dd+3] * inv);
        *(float4*)(dst + dd) = w4;
    }
}

// ---------------------------------------------------------------------------
extern "C" void kernel_launch(void* const* d_in, const int* in_sizes, int n_in,
                              void* d_out, int out_size)
{
    const float* x     = (const float*)d_in[0];
    const float* qkv_w = (const float*)d_in[1];
    const float* qkv_b = (const float*)d_in[2];
    const float* out_w = (const float*)d_in[3];
    const float* out_b = (const float*)d_in[4];
    float* out = (float*)d_out;

    cudaFuncSetAttribute(attn_kernel,
                         cudaFuncAttributeMaxDynamicSharedMemorySize,
                         ATT_SMEM_BYTES);

    qkv_gemm_kernel<<<dim3(QKV_N / 64, MTOT / 64), 256>>>(x, qkv_w, qkv_b);
    attn_kernel<<<dim3(SEQ / BM, BATCH * NHEAD), 256, ATT_SMEM_BYTES>>>();
    proj_gemm_kernel<<<dim3(EMBED / 64, MTOT / 64), 256>>>(out_w, out_b, out);
}

// round 3
// speedup vs baseline: 1.6959x; 1.6959x over previous
#include <cuda_runtime.h>
#include <math.h>

#define EMBED 1024
#define NHEAD 16
#define HD    64
#define BATCH 4
#define SEQ   2048
#define MTOT  (BATCH*SEQ)     // 8192
#define QKV_N (3*EMBED)       // 3072

// Scratch (device globals: no allocations allowed)
__device__ float g_Q[(size_t)BATCH*NHEAD*SEQ*HD];   // [bh][s][d], pre-scaled by 1/8
__device__ float g_K[(size_t)BATCH*NHEAD*SEQ*HD];
__device__ float g_V[(size_t)BATCH*NHEAD*SEQ*HD];
__device__ float g_AO[(size_t)BATCH*SEQ*EMBED];     // attention out, [b*s][h*64+d]

// ---------------------------------------------------------------------------
// SGEMM core: C = A(MxK) @ W(NxK)^T, 128x128 tile, 256 threads, 8x8 microtile.
// As/Bs stored k-major [kk][m] with stride 132 (decorrelates row banks).
// ---------------------------------------------------------------------------
#define GS 132

__device__ __forceinline__ void gemm128_core(
    const float4* __restrict__ A4, const float4* __restrict__ W4,
    int m0, int n0, float As[16][GS], float Bs[16][GS],
    float acc[8][8], int tid)
{
    const int tx = tid & 15, ty = tid >> 4;
    #pragma unroll
    for (int i = 0; i < 8; i++)
        #pragma unroll
        for (int j = 0; j < 8; j++) acc[i][j] = 0.f;

    for (int k0 = 0; k0 < EMBED; k0 += 16) {
        #pragma unroll
        for (int i = 0; i < 2; i++) {
            int idx = i * 256 + tid;
            int r = idx >> 2, c4 = idx & 3;
            float4 av = A4[(size_t)(m0 + r) * (EMBED/4) + (k0 >> 2) + c4];
            float4 bv = W4[(size_t)(n0 + r) * (EMBED/4) + (k0 >> 2) + c4];
            As[c4*4+0][r] = av.x; As[c4*4+1][r] = av.y;
            As[c4*4+2][r] = av.z; As[c4*4+3][r] = av.w;
            Bs[c4*4+0][r] = bv.x; Bs[c4*4+1][r] = bv.y;
            Bs[c4*4+2][r] = bv.z; Bs[c4*4+3][r] = bv.w;
        }
        __syncthreads();
        #pragma unroll
        for (int kk = 0; kk < 16; kk++) {
            float4 a0 = *(const float4*)&As[kk][ty*8];
            float4 a1 = *(const float4*)&As[kk][ty*8+4];
            float4 b0 = *(const float4*)&Bs[kk][tx*8];
            float4 b1 = *(const float4*)&Bs[kk][tx*8+4];
            float ar[8] = {a0.x,a0.y,a0.z,a0.w,a1.x,a1.y,a1.z,a1.w};
            float br[8] = {b0.x,b0.y,b0.z,b0.w,b1.x,b1.y,b1.z,b1.w};
            #pragma unroll
            for (int i = 0; i < 8; i++)
                #pragma unroll
                for (int j = 0; j < 8; j++) acc[i][j] += ar[i] * br[j];
        }
        __syncthreads();
    }
}

__global__ __launch_bounds__(256) void qkv_gemm_kernel(
    const float* __restrict__ A, const float* __restrict__ W,
    const float* __restrict__ bias)
{
    __shared__ __align__(16) float As[16][GS];
    __shared__ __align__(16) float Bs[16][GS];
    const int tid = threadIdx.x;
    const int tx = tid & 15, ty = tid >> 4;
    const int m0 = blockIdx.y * 128, n0 = blockIdx.x * 128;
    float acc[8][8];
    gemm128_core((const float4*)A, (const float4*)W, m0, n0, As, Bs, acc, tid);

    // Epilogue: bias + head split. n -> h=n/192, r=n%192; r/64 selects Q|K|V, d=r%64
    #pragma unroll
    for (int j = 0; j < 8; j++) {
        int n = n0 + tx*8 + j;
        int h = n / 192;
        int r = n - h * 192;
        int w = r >> 6;
        int d = r & 63;
        float bsv = bias[n];
        #pragma unroll
        for (int i = 0; i < 8; i++) {
            int m = m0 + ty*8 + i;
            int b = m >> 11, s = m & (SEQ - 1);
            size_t idx = (((size_t)(b * NHEAD + h)) * SEQ + s) * HD + d;
            float v = acc[i][j] + bsv;
            if (w == 0)      g_Q[idx] = v * 0.125f;   // 1/sqrt(64)
            else if (w == 1) g_K[idx] = v;
            else             g_V[idx] = v;
        }
    }
}

__global__ __launch_bounds__(256) void proj_gemm_kernel(
    const float* __restrict__ W, const float* __restrict__ bias,
    float* __restrict__ C)
{
    __shared__ __align__(16) float As[16][GS];
    __shared__ __align__(16) float Bs[16][GS];
    const int tid = threadIdx.x;
    const int tx = tid & 15, ty = tid >> 4;
    const int m0 = blockIdx.y * 128, n0 = blockIdx.x * 128;
    float acc[8][8];
    gemm128_core((const float4*)g_AO, (const float4*)W, m0, n0, As, Bs, acc, tid);

    float4 bb0 = *(const float4*)&bias[n0 + tx*8];
    float4 bb1 = *(const float4*)&bias[n0 + tx*8 + 4];
    float br8[8] = {bb0.x,bb0.y,bb0.z,bb0.w,bb1.x,bb1.y,bb1.z,bb1.w};
    #pragma unroll
    for (int i = 0; i < 8; i++) {
        int m = m0 + ty*8 + i;
        float4 o0, o1;
        o0.x = acc[i][0]+br8[0]; o0.y = acc[i][1]+br8[1];
        o0.z = acc[i][2]+br8[2]; o0.w = acc[i][3]+br8[3];
        o1.x = acc[i][4]+br8[4]; o1.y = acc[i][5]+br8[5];
        o1.z = acc[i][6]+br8[6]; o1.w = acc[i][7]+br8[7];
        *(float4*)&C[(size_t)m * EMBED + n0 + tx*8]     = o0;
        *(float4*)&C[(size_t)m * EMBED + n0 + tx*8 + 4] = o1;
    }
}

// ---------------------------------------------------------------------------
// Flash attention fp32. Block: 128 queries x one (b,h); 256 threads.
// Thread = (query q, d/j-half). K stored TRANSPOSED (Kt[d][jcol]) so the QK
// loop loads K via broadcast LDS.128. V rows 16B-aligned with a +36 half
// offset (not +33 skew) so PV loads are broadcast LDS.128 too.
// jcol/dcol mapping: c + (c>>5)*4  (0..31 -> 0..31, 32..63 -> 36..67).
// ---------------------------------------------------------------------------
#define BM 128
#define BN 64
#define QS_STRIDE 65
#define KT_STRIDE 68
#define VS_STRIDE 68
#define PS_STRIDE 67
#define QS_SZ (BM*QS_STRIDE)   // 8320
#define KT_SZ (HD*KT_STRIDE)   // 4352
#define VS_SZ (BN*VS_STRIDE)   // 4352
#define PS_SZ (BM*PS_STRIDE)   // 8576
#define ATT_SMEM_FLOATS (QS_SZ + KT_SZ + VS_SZ + PS_SZ)
#define ATT_SMEM_BYTES  (ATT_SMEM_FLOATS * 4)   // 102,400 B -> 2 blocks/SM

__global__ __launch_bounds__(256) void attn_kernel()
{
    extern __shared__ float smbuf[];
    float* Qs = smbuf;
    float* Kt = Qs + QS_SZ;
    float* Vs = Kt + KT_SZ;
    float* Ps = Vs + VS_SZ;

    const int tid  = threadIdx.x;
    const int q    = tid >> 1;
    const int half = tid & 1;
    const int bh   = blockIdx.y;
    const int q0   = blockIdx.x * BM;

    // Load Q tile [128][64] (pre-scaled by 1/8 at QKV epilogue)
    const float4* Qg = (const float4*)(g_Q + ((size_t)bh * SEQ + q0) * HD);
    #pragma unroll
    for (int i = 0; i < 8; i++) {
        int idx = i * 256 + tid;
        int r = idx >> 4, c4 = idx & 15;
        float4 v = Qg[idx];
        float* dst = &Qs[r * QS_STRIDE + c4 * 4];
        dst[0] = v.x; dst[1] = v.y; dst[2] = v.z; dst[3] = v.w;
    }

    const float4* Kg = (const float4*)(g_K + (size_t)bh * SEQ * HD);
    const float4* Vg = (const float4*)(g_V + (size_t)bh * SEQ * HD);

    float mrun = -INFINITY, lrun = 0.f;
    float o[32];
    #pragma unroll
    for (int dd = 0; dd < 32; dd++) o[dd] = 0.f;

    const float* qrow = &Qs[q * QS_STRIDE];
    const float* kb   = Kt + half * 36;   // j-half base (aligned, distinct banks)
    const float* vb   = Vs + half * 36;   // d-half base
    float*       prow = &Ps[q * PS_STRIDE];
    const int    pskew = half * 33;       // write col: half*33 + jj

    for (int t = 0; t < SEQ / BN; t++) {
        __syncthreads();   // prior iteration's Kt/Vs reads done before overwrite
        #pragma unroll
        for (int i = 0; i < 4; i++) {
            int idx = i * 256 + tid;
            int r = idx >> 4, c4 = idx & 15, db = c4 * 4;
            float4 kv = Kg[(size_t)(t * BN) * 16 + idx];
            float4 vv = Vg[(size_t)(t * BN) * 16 + idx];
            // K transposed: Kt[d][jcol], jcol = r + (r>>5)*4
            int jcol = r + ((r >> 5) << 2);
            Kt[(db+0) * KT_STRIDE + jcol] = kv.x;
            Kt[(db+1) * KT_STRIDE + jcol] = kv.y;
            Kt[(db+2) * KT_STRIDE + jcol] = kv.z;
            Kt[(db+3) * KT_STRIDE + jcol] = kv.w;
            // V row-major aligned: Vs[r][dcol], dcol = db + (db>>5)*4
            float* vd = &Vs[r * VS_STRIDE + db + ((db >> 5) << 2)];
            vd[0] = vv.x; vd[1] = vv.y; vd[2] = vv.z; vd[3] = vv.w;
        }
        __syncthreads();

        // Scores: 32 j's per thread over full d=64, K loads are LDS.128 broadcasts
        float p[32];
        #pragma unroll
        for (int jj = 0; jj < 32; jj++) p[jj] = 0.f;
        #pragma unroll 8
        for (int d = 0; d < HD; d++) {
            float qv = qrow[d];
            const float* kr = kb + d * KT_STRIDE;
            #pragma unroll
            for (int j4 = 0; j4 < 8; j4++) {
                float4 kv = *(const float4*)(kr + j4 * 4);
                p[j4*4+0] += qv * kv.x;
                p[j4*4+1] += qv * kv.y;
                p[j4*4+2] += qv * kv.z;
                p[j4*4+3] += qv * kv.w;
            }
        }

        // Online softmax (pairwise over the two halves via shfl)
        float mx = p[0];
        #pragma unroll
        for (int jj = 1; jj < 32; jj++) mx = fmaxf(mx, p[jj]);
        mx = fmaxf(mx, __shfl_xor_sync(0xffffffffu, mx, 1));
        float mnew = fmaxf(mrun, mx);
        float corr = __expf(mrun - mnew);
        float ls = 0.f;
        #pragma unroll
        for (int jj = 0; jj < 32; jj++) {
            p[jj] = __expf(p[jj] - mnew);
            ls += p[jj];
        }
        ls += __shfl_xor_sync(0xffffffffu, ls, 1);
        lrun = lrun * corr + ls;
        mrun = mnew;
        #pragma unroll
        for (int dd = 0; dd < 32; dd++) o[dd] *= corr;

        // Stage probs to smem (warp-local exchange between halves)
        #pragma unroll
        for (int jj = 0; jj < 32; jj++) prow[pskew + jj] = p[jj];
        __syncwarp();

        // PV: O[d-half] += P[q][j] * V[j][d-half]; V loads are LDS.128 broadcasts
        #pragma unroll 2
        for (int j = 0; j < BN; j++) {
            float pj = prow[j + (j >> 5)];
            const float* vr = vb + j * VS_STRIDE;
            #pragma unroll
            for (int d4 = 0; d4 < 8; d4++) {
                float4 vv = *(const float4*)(vr + d4 * 4);
                o[d4*4+0] += pj * vv.x;
                o[d4*4+1] += pj * vv.y;
                o[d4*4+2] += pj * vv.z;
                o[d4*4+3] += pj * vv.w;
            }
        }
        __syncwarp();  // partner must not overwrite prow before our reads finish
    }

    float inv = 1.f / lrun;
    int b = bh >> 4, h = bh & 15;
    float* dst = g_AO + ((size_t)(b * SEQ + q0 + q)) * EMBED + h * HD + half * 32;
    #pragma unroll
    for (int dd = 0; dd < 32; dd += 4) {
        float4 w4 = make_float4(o[dd] * inv, o[dd+1] * inv, o[dd+2] * inv, o[dd+3] * inv);
        *(float4*)(dst + dd) = w4;
    }
}

// ---------------------------------------------------------------------------
extern "C" void kernel_launch(void* const* d_in, const int* in_sizes, int n_in,
                              void* d_out, int out_size)
{
    const float* x     = (const float*)d_in[0];
    const float* qkv_w = (const float*)d_in[1];
    const float* qkv_b = (const float*)d_in[2];
    const float* out_w = (const float*)d_in[3];
    const float* out_b = (const float*)d_in[4];
    float* out = (float*)d_out;

    cudaFuncSetAttribute(attn_kernel,
                         cudaFuncAttributeMaxDynamicSharedMemorySize,
                         ATT_SMEM_BYTES);

    qkv_gemm_kernel<<<dim3(QKV_N / 128, MTOT / 128), 256>>>(x, qkv_w, qkv_b);
    attn_kernel<<<dim3(SEQ / BM, BATCH * NHEAD), 256, ATT_SMEM_BYTES>>>();
    proj_gemm_kernel<<<dim3(EMBED / 128, MTOT / 128), 256>>>(out_w, out_b, out);
}

// round 6
// speedup vs baseline: 2.1340x; 1.2583x over previous
#include <cuda_runtime.h>
#include <cuda_bf16.h>
#include <math.h>
#include <stdint.h>

#define EMBED 1024
#define NHEAD 16
#define HD    64
#define BATCH 4
#define SEQ   2048
#define MTOT  (BATCH*SEQ)     // 8192
#define QKV_N (3*EMBED)       // 3072
#define KCAT  (3*EMBED)       // split-concat K = 3072

// ---------------- scratch (device globals; no allocs allowed) ---------------
__device__ float g_Q[(size_t)BATCH*NHEAD*SEQ*HD];   // [bh][s][d], pre-scaled 1/8
__device__ float g_K[(size_t)BATCH*NHEAD*SEQ*HD];
__device__ float g_V[(size_t)BATCH*NHEAD*SEQ*HD];
__device__ float g_AO[(size_t)MTOT*EMBED];          // attention out [m][e]
__device__ __nv_bfloat16 g_Xc  [(size_t)MTOT*KCAT];   // x split-cat      (A-style)
__device__ __nv_bfloat16 g_Wqc [(size_t)QKV_N*KCAT];  // qkv_w split-cat  (W-style)
__device__ __nv_bfloat16 g_Woc [(size_t)EMBED*KCAT];  // out_w split-cat  (W-style)
__device__ __nv_bfloat16 g_AOc [(size_t)MTOT*KCAT];   // AO split-cat     (A-style)

// ---------------- helpers ---------------------------------------------------
__device__ __forceinline__ uint32_t smem_u32(const void* p) {
    uint32_t a;
    asm("{ .reg .u64 t; cvta.to.shared.u64 t, %1; cvt.u32.u64 %0, t; }" : "=r"(a) : "l"(p));
    return a;
}
__device__ __forceinline__ void ldm_x4(uint32_t* r, uint32_t addr) {
    asm volatile("ldmatrix.sync.aligned.m8n8.x4.shared.b16 {%0,%1,%2,%3}, [%4];"
        : "=r"(r[0]), "=r"(r[1]), "=r"(r[2]), "=r"(r[3]) : "r"(addr));
}
__device__ __forceinline__ void mma_bf16(float* d, const uint32_t* a,
                                         uint32_t b0, uint32_t b1) {
    asm volatile("mma.sync.aligned.m16n8k16.row.col.f32.bf16.bf16.f32 "
        "{%0,%1,%2,%3}, {%4,%5,%6,%7}, {%8,%9}, {%0,%1,%2,%3};"
        : "+f"(d[0]), "+f"(d[1]), "+f"(d[2]), "+f"(d[3])
        : "r"(a[0]), "r"(a[1]), "r"(a[2]), "r"(a[3]), "r"(b0), "r"(b1));
}

// ---------------- split-bf16 conversion -------------------------------------
// A-style rows: [hi | lo | hi] ; W-style rows: [hi | hi | lo]
// => A@W^T over KCAT = Ah*Wh + Al*Wh + Ah*Wl  (drops only 2^-16-scale Al*Wl)
__device__ __forceinline__ void split_body(const float* __restrict__ src,
                                           __nv_bfloat16* __restrict__ dst,
                                           size_t nrows, int wstyle)
{
    size_t total = nrows * (EMBED / 8);
    for (size_t i = (size_t)blockIdx.x * blockDim.x + threadIdx.x;
         i < total; i += (size_t)gridDim.x * blockDim.x) {
        size_t row = i >> 7;
        int c8 = (int)(i & 127) * 8;
        const float4* s = (const float4*)(src + row * EMBED + c8);
        float4 v0 = s[0], v1 = s[1];
        float v[8] = {v0.x,v0.y,v0.z,v0.w,v1.x,v1.y,v1.z,v1.w};
        uint16_t hb[8], lb[8];
        #pragma unroll
        for (int j = 0; j < 8; j++) {
            __nv_bfloat16 h = __float2bfloat16(v[j]);
            __nv_bfloat16 l = __float2bfloat16(v[j] - __bfloat162float(h));
            hb[j] = __bfloat16_as_ushort(h);
            lb[j] = __bfloat16_as_ushort(l);
        }
        uint4 hp, lp;
        hp.x = hb[0] | ((uint32_t)hb[1]<<16); hp.y = hb[2] | ((uint32_t)hb[3]<<16);
        hp.z = hb[4] | ((uint32_t)hb[5]<<16); hp.w = hb[6] | ((uint32_t)hb[7]<<16);
        lp.x = lb[0] | ((uint32_t)lb[1]<<16); lp.y = lb[2] | ((uint32_t)lb[3]<<16);
        lp.z = lb[4] | ((uint32_t)lb[5]<<16); lp.w = lb[6] | ((uint32_t)lb[7]<<16);
        __nv_bfloat16* base = dst + row * KCAT + c8;
        *(uint4*)(base)             = hp;
        *(uint4*)(base + EMBED)     = wstyle ? hp : lp;
        *(uint4*)(base + 2*EMBED)   = wstyle ? lp : hp;
    }
}
__global__ __launch_bounds__(256) void split_x_kernel(const float* __restrict__ s)
{ split_body(s, g_Xc, MTOT, 0); }
__global__ __launch_bounds__(256) void split_wq_kernel(const float* __restrict__ s)
{ split_body(s, g_Wqc, QKV_N, 1); }
__global__ __launch_bounds__(256) void split_wo_kernel(const float* __restrict__ s)
{ split_body(s, g_Woc, EMBED, 1); }
__global__ __launch_bounds__(256) void split_ao_kernel()
{ split_body(g_AO, g_AOc, MTOT, 0); }

// ---------------- HMMA GEMM core: D[128x128] = A[128xKCAT] @ W[128xKCAT]^T --
// 8 warps as 4(m) x 2(n): warp computes 32x64 via m16n8k16 (2 mtiles x 8 ntiles).
// smem: bf16 [128][40] per buffer (80B row stride -> conflict-free ldmatrix).
#define BKW 32
#define NKB (KCAT / BKW)      // 96
#define SSTR 40
#define BUFE (128 * SSTR)     // elements per buffer

__device__ __forceinline__ void hgemm_core(
    const uint4* __restrict__ A, const uint4* __restrict__ W,
    int m0, int n0, float acc[2][8][4])
{
    __shared__ __align__(16) __nv_bfloat16 sA[2][BUFE];
    __shared__ __align__(16) __nv_bfloat16 sW[2][BUFE];
    const int tid = threadIdx.x, lane = tid & 31, wid = tid >> 5;
    const int mw = wid & 3, nw = wid >> 2;
    const int lr = tid >> 2, lc = tid & 3;
    const size_t RS = KCAT / 8;     // 384 uint4 per row

    #pragma unroll
    for (int i = 0; i < 2; i++)
        #pragma unroll
        for (int j = 0; j < 8; j++)
            #pragma unroll
            for (int k = 0; k < 4; k++) acc[i][j][k] = 0.f;

    uint4 pa0, pa1, pw0, pw1;
    pa0 = A[(size_t)(m0 + lr) * RS + lc];
    pa1 = A[(size_t)(m0 + 64 + lr) * RS + lc];
    pw0 = W[(size_t)(n0 + lr) * RS + lc];
    pw1 = W[(size_t)(n0 + 64 + lr) * RS + lc];
    *(uint4*)&sA[0][lr * SSTR + lc * 8]        = pa0;
    *(uint4*)&sA[0][(64 + lr) * SSTR + lc * 8] = pa1;
    *(uint4*)&sW[0][lr * SSTR + lc * 8]        = pw0;
    *(uint4*)&sW[0][(64 + lr) * SSTR + lc * 8] = pw1;
    __syncthreads();

    const uint32_t aB = smem_u32(&sA[0][0]);
    const uint32_t wB = smem_u32(&sW[0][0]);
    // A frag addr: rows (lane&15), k-8-group (lane>>4)
    const uint32_t aOff = ((mw * 32 + (lane & 15)) * SSTR + ((lane >> 4) << 3)) * 2;
    // B frag addr: n-row ((lane>>4)&1)*8 + (lane&7), k-8-group (lane>>3)&1
    const uint32_t wOff = ((nw * 64 + (((lane >> 4) & 1) << 3) + (lane & 7)) * SSTR
                          + (((lane >> 3) & 1) << 3)) * 2;

    for (int kb = 0; kb < NKB; kb++) {
        int cur = kb & 1;
        if (kb + 1 < NKB) {
            pa0 = A[(size_t)(m0 + lr) * RS + (kb + 1) * 4 + lc];
            pa1 = A[(size_t)(m0 + 64 + lr) * RS + (kb + 1) * 4 + lc];
            pw0 = W[(size_t)(n0 + lr) * RS + (kb + 1) * 4 + lc];
            pw1 = W[(size_t)(n0 + 64 + lr) * RS + (kb + 1) * 4 + lc];
        }
        uint32_t aCur = aB + cur * (BUFE * 2) + aOff;
        uint32_t wCur = wB + cur * (BUFE * 2) + wOff;
        #pragma unroll
        for (int kk = 0; kk < 2; kk++) {        // two k16 steps
            uint32_t af0[4], af1[4];
            ldm_x4(af0, aCur + kk * 32);
            ldm_x4(af1, aCur + (16 * SSTR) * 2 + kk * 32);
            #pragma unroll
            for (int g = 0; g < 4; g++) {       // n16 groups
                uint32_t bf[4];
                ldm_x4(bf, wCur + (g * 16 * SSTR) * 2 + kk * 32);
                mma_bf16(acc[0][2*g+0], af0, bf[0], bf[1]);
                mma_bf16(acc[1][2*g+0], af1, bf[0], bf[1]);
                mma_bf16(acc[0][2*g+1], af0, bf[2], bf[3]);
                mma_bf16(acc[1][2*g+1], af1, bf[2], bf[3]);
            }
        }
        if (kb + 1 < NKB) {
            int nxt = cur ^ 1;
            *(uint4*)&sA[nxt][lr * SSTR + lc * 8]        = pa0;
            *(uint4*)&sA[nxt][(64 + lr) * SSTR + lc * 8] = pa1;
            *(uint4*)&sW[nxt][lr * SSTR + lc * 8]        = pw0;
            *(uint4*)&sW[nxt][(64 + lr) * SSTR + lc * 8] = pw1;
            __syncthreads();
        }
    }
}

// qkv: [8192 x 3072] -> bias + head-split scatter into g_Q/g_K/g_V
__global__ __launch_bounds__(256, 2) void hq_qkv_kernel(const float* __restrict__ bias)
{
    float acc[2][8][4];
    const int m0 = blockIdx.y * 128, n0 = blockIdx.x * 128;
    hgemm_core((const uint4*)g_Xc, (const uint4*)g_Wqc, m0, n0, acc);

    const int lane = threadIdx.x & 31, wid = threadIdx.x >> 5;
    const int mw = wid & 3, nw = wid >> 2;
    #pragma unroll
    for (int mt = 0; mt < 2; mt++) {
        int mlo = m0 + mw * 32 + mt * 16 + (lane >> 2);
        int mhi = mlo + 8;
        int blo = mlo >> 11, slo = mlo & (SEQ - 1);
        int bhi = mhi >> 11, shi = mhi & (SEQ - 1);
        #pragma unroll
        for (int nt = 0; nt < 8; nt++) {
            int n = n0 + nw * 64 + nt * 8 + (lane & 3) * 2;
            int h = n / 192;
            int r = n - h * 192;
            int w = r >> 6;
            int d = r & 63;
            float2 bv = *(const float2*)&bias[n];
            float sc = (w == 0) ? 0.125f : 1.0f;
            float* buf = (w == 0) ? g_Q : (w == 1) ? g_K : g_V;
            size_t i0 = (((size_t)(blo * NHEAD + h)) * SEQ + slo) * HD + d;
            size_t i1 = (((size_t)(bhi * NHEAD + h)) * SEQ + shi) * HD + d;
            float2 v0 = make_float2((acc[mt][nt][0] + bv.x) * sc,
                                    (acc[mt][nt][1] + bv.y) * sc);
            float2 v1 = make_float2((acc[mt][nt][2] + bv.x) * sc,
                                    (acc[mt][nt][3] + bv.y) * sc);
            *(float2*)&buf[i0] = v0;
            *(float2*)&buf[i1] = v1;
        }
    }
}

// proj: [8192 x 1024] -> bias + store to d_out
__global__ __launch_bounds__(256, 2) void hq_proj_kernel(const float* __restrict__ bias,
                                                         float* __restrict__ C)
{
    float acc[2][8][4];
    const int m0 = blockIdx.y * 128, n0 = blockIdx.x * 128;
    hgemm_core((const uint4*)g_AOc, (const uint4*)g_Woc, m0, n0, acc);

    const int lane = threadIdx.x & 31, wid = threadIdx.x >> 5;
    const int mw = wid & 3, nw = wid >> 2;
    #pragma unroll
    for (int mt = 0; mt < 2; mt++) {
        int mlo = m0 + mw * 32 + mt * 16 + (lane >> 2);
        int mhi = mlo + 8;
        #pragma unroll
        for (int nt = 0; nt < 8; nt++) {
            int n = n0 + nw * 64 + nt * 8 + (lane & 3) * 2;
            float2 bv = *(const float2*)&bias[n];
            *(float2*)&C[(size_t)mlo * EMBED + n] =
                make_float2(acc[mt][nt][0] + bv.x, acc[mt][nt][1] + bv.y);
            *(float2*)&C[(size_t)mhi * EMBED + n] =
                make_float2(acc[mt][nt][2] + bv.x, acc[mt][nt][3] + bv.y);
        }
    }
}

// ---------------------------------------------------------------------------
// Flash attention fp32 (proven round-3 kernel, unchanged)
// ---------------------------------------------------------------------------
#define BM 128
#define BN 64
#define QS_STRIDE 65
#define KT_STRIDE 68
#define VS_STRIDE 68
#define PS_STRIDE 67
#define QS_SZ (BM*QS_STRIDE)
#define KT_SZ (HD*KT_STRIDE)
#define VS_SZ (BN*VS_STRIDE)
#define PS_SZ (BM*PS_STRIDE)
#define ATT_SMEM_FLOATS (QS_SZ + KT_SZ + VS_SZ + PS_SZ)
#define ATT_SMEM_BYTES  (ATT_SMEM_FLOATS * 4)

__global__ __launch_bounds__(256) void attn_kernel()
{
    extern __shared__ float smbuf[];
    float* Qs = smbuf;
    float* Kt = Qs + QS_SZ;
    float* Vs = Kt + KT_SZ;
    float* Ps = Vs + VS_SZ;

    const int tid  = threadIdx.x;
    const int q    = tid >> 1;
    const int half = tid & 1;
    const int bh   = blockIdx.y;
    const int q0   = blockIdx.x * BM;

    const float4* Qg = (const float4*)(g_Q + ((size_t)bh * SEQ + q0) * HD);
    #pragma unroll
    for (int i = 0; i < 8; i++) {
        int idx = i * 256 + tid;
        int r = idx >> 4, c4 = idx & 15;
        float4 v = Qg[idx];
        float* dst = &Qs[r * QS_STRIDE + c4 * 4];
        dst[0] = v.x; dst[1] = v.y; dst[2] = v.z; dst[3] = v.w;
    }

    const float4* Kg = (const float4*)(g_K + (size_t)bh * SEQ * HD);
    const float4* Vg = (const float4*)(g_V + (size_t)bh * SEQ * HD);

    float mrun = -INFINITY, lrun = 0.f;
    float o[32];
    #pragma unroll
    for (int dd = 0; dd < 32; dd++) o[dd] = 0.f;

    const float* qrow = &Qs[q * QS_STRIDE];
    const float* kb   = Kt + half * 36;
    const float* vb   = Vs + half * 36;
    float*       prow = &Ps[q * PS_STRIDE];
    const int    pskew = half * 33;

    for (int t = 0; t < SEQ / BN; t++) {
        __syncthreads();
        #pragma unroll
        for (int i = 0; i < 4; i++) {
            int idx = i * 256 + tid;
            int r = idx >> 4, c4 = idx & 15, db = c4 * 4;
            float4 kv = Kg[(size_t)(t * BN) * 16 + idx];
            float4 vv = Vg[(size_t)(t * BN) * 16 + idx];
            int jcol = r + ((r >> 5) << 2);
            Kt[(db+0) * KT_STRIDE + jcol] = kv.x;
            Kt[(db+1) * KT_STRIDE + jcol] = kv.y;
            Kt[(db+2) * KT_STRIDE + jcol] = kv.z;
            Kt[(db+3) * KT_STRIDE + jcol] = kv.w;
            float* vd = &Vs[r * VS_STRIDE + db + ((db >> 5) << 2)];
            vd[0] = vv.x; vd[1] = vv.y; vd[2] = vv.z; vd[3] = vv.w;
        }
        __syncthreads();

        float p[32];
        #pragma unroll
        for (int jj = 0; jj < 32; jj++) p[jj] = 0.f;
        #pragma unroll 8
        for (int d = 0; d < HD; d++) {
            float qv = qrow[d];
            const float* kr = kb + d * KT_STRIDE;
            #pragma unroll
            for (int j4 = 0; j4 < 8; j4++) {
                float4 kv = *(const float4*)(kr + j4 * 4);
                p[j4*4+0] += qv * kv.x;
                p[j4*4+1] += qv * kv.y;
                p[j4*4+2] += qv * kv.z;
                p[j4*4+3] += qv * kv.w;
            }
        }

        float mx = p[0];
        #pragma unroll
        for (int jj = 1; jj < 32; jj++) mx = fmaxf(mx, p[jj]);
        mx = fmaxf(mx, __shfl_xor_sync(0xffffffffu, mx, 1));
        float mnew = fmaxf(mrun, mx);
        float corr = __expf(mrun - mnew);
        float ls = 0.f;
        #pragma unroll
        for (int jj = 0; jj < 32; jj++) {
            p[jj] = __expf(p[jj] - mnew);
            ls += p[jj];
        }
        ls += __shfl_xor_sync(0xffffffffu, ls, 1);
        lrun = lrun * corr + ls;
        mrun = mnew;
        #pragma unroll
        for (int dd = 0; dd < 32; dd++) o[dd] *= corr;

        #pragma unroll
        for (int jj = 0; jj < 32; jj++) prow[pskew + jj] = p[jj];
        __syncwarp();

        #pragma unroll 2
        for (int j = 0; j < BN; j++) {
            float pj = prow[j + (j >> 5)];
            const float* vr = vb + j * VS_STRIDE;
            #pragma unroll
            for (int d4 = 0; d4 < 8; d4++) {
                float4 vv = *(const float4*)(vr + d4 * 4);
                o[d4*4+0] += pj * vv.x;
                o[d4*4+1] += pj * vv.y;
                o[d4*4+2] += pj * vv.z;
                o[d4*4+3] += pj * vv.w;
            }
        }
        __syncwarp();
    }

    float inv = 1.f / lrun;
    int b = bh >> 4, h = bh & 15;
    float* dst = g_AO + ((size_t)(b * SEQ + q0 + q)) * EMBED + h * HD + half * 32;
    #pragma unroll
    for (int dd = 0; dd < 32; dd += 4) {
        float4 w4 = make_float4(o[dd] * inv, o[dd+1] * inv, o[dd+2] * inv, o[dd+3] * inv);
        *(float4*)(dst + dd) = w4;
    }
}

// ---------------------------------------------------------------------------
extern "C" void kernel_launch(void* const* d_in, const int* in_sizes, int n_in,
                              void* d_out, int out_size)
{
    const float* x     = (const float*)d_in[0];
    const float* qkv_w = (const float*)d_in[1];
    const float* qkv_b = (const float*)d_in[2];
    const float* out_w = (const float*)d_in[3];
    const float* out_b = (const float*)d_in[4];
    float* out = (float*)d_out;

    cudaFuncSetAttribute(attn_kernel,
                         cudaFuncAttributeMaxDynamicSharedMemorySize, ATT_SMEM_BYTES);

    split_x_kernel <<<2048, 256>>>(x);
    split_wq_kernel<<<1536, 256>>>(qkv_w);
    split_wo_kernel<<<512,  256>>>(out_w);

    hq_qkv_kernel<<<dim3(QKV_N/128, MTOT/128), 256>>>(qkv_b);

    attn_kernel<<<dim3(SEQ / BM, BATCH * NHEAD), 256, ATT_SMEM_BYTES>>>();

    split_ao_kernel<<<2048, 256>>>();
    hq_proj_kernel<<<dim3(EMBED/128, MTOT/128), 256>>>(out_b, out);
}

// round 12
// speedup vs baseline: 4.0549x; 1.9002x over previous
#include <cuda_runtime.h>
#include <cuda_bf16.h>
#include <math.h>
#include <stdint.h>

#define EMBED 1024
#define NHEAD 16
#define HD    64
#define BATCH 4
#define SEQ   2048
#define MTOT  (BATCH*SEQ)     // 8192
#define QKV_N (3*EMBED)       // 3072
#define KCAT  (3*EMBED)       // split-concat K = 3072

// ---------------- scratch (device globals; no allocs allowed) ---------------
__device__ __align__(16) __nv_bfloat16 g_Qh[(size_t)BATCH*NHEAD*SEQ*HD]; // pre-scaled 1/8
__device__ __align__(16) __nv_bfloat16 g_Ql[(size_t)BATCH*NHEAD*SEQ*HD];
__device__ __align__(16) __nv_bfloat16 g_Kh[(size_t)BATCH*NHEAD*SEQ*HD];
__device__ __align__(16) __nv_bfloat16 g_Kl[(size_t)BATCH*NHEAD*SEQ*HD];
__device__ __align__(16) __nv_bfloat16 g_Vh[(size_t)BATCH*NHEAD*SEQ*HD];
__device__ __align__(16) __nv_bfloat16 g_Vl[(size_t)BATCH*NHEAD*SEQ*HD];
__device__ __align__(16) __nv_bfloat16 g_Xc [(size_t)MTOT*KCAT];    // x split-cat (A-style)
__device__ __align__(16) __nv_bfloat16 g_Wqc[(size_t)QKV_N*KCAT];   // qkv_w (W-style)
__device__ __align__(16) __nv_bfloat16 g_Woc[(size_t)EMBED*KCAT];   // out_w (W-style)
__device__ __align__(16) __nv_bfloat16 g_AOc[(size_t)MTOT*KCAT];    // attn out (A-style)

// ---------------- helpers ---------------------------------------------------
__device__ __forceinline__ uint32_t smem_u32(const void* p) {
    uint32_t a;
    asm("{ .reg .u64 t; cvta.to.shared.u64 t, %1; cvt.u32.u64 %0, t; }" : "=r"(a) : "l"(p));
    return a;
}
__device__ __forceinline__ void ldm_x4(uint32_t* r, uint32_t addr) {
    asm volatile("ldmatrix.sync.aligned.m8n8.x4.shared.b16 {%0,%1,%2,%3}, [%4];"
        : "=r"(r[0]), "=r"(r[1]), "=r"(r[2]), "=r"(r[3]) : "r"(addr));
}
__device__ __forceinline__ void mma_bf16(float* d, const uint32_t* a,
                                         uint32_t b0, uint32_t b1) {
    asm volatile("mma.sync.aligned.m16n8k16.row.col.f32.bf16.bf16.f32 "
        "{%0,%1,%2,%3}, {%4,%5,%6,%7}, {%8,%9}, {%0,%1,%2,%3};"
        : "+f"(d[0]), "+f"(d[1]), "+f"(d[2]), "+f"(d[3])
        : "r"(a[0]), "r"(a[1]), "r"(a[2]), "r"(a[3]), "r"(b0), "r"(b1));
}
// split fp32 pair -> bf16x2 hi + bf16x2 lo (low half = first value)
__device__ __forceinline__ void bsplit2(uint32_t& hi, uint32_t& lo, float x, float y) {
    __nv_bfloat16 hx = __float2bfloat16(x), hy = __float2bfloat16(y);
    __nv_bfloat162 h2; h2.x = hx; h2.y = hy;
    hi = *(uint32_t*)&h2;
    __nv_bfloat162 l2 = __floats2bfloat162_rn(x - __bfloat162float(hx),
                                              y - __bfloat162float(hy));
    lo = *(uint32_t*)&l2;
}

// ---------------- split-bf16 conversion (GEMM operands) ---------------------
__device__ __forceinline__ void split_body(const float* __restrict__ src,
                                           __nv_bfloat16* __restrict__ dst,
                                           size_t nrows, int wstyle)
{
    size_t total = nrows * (EMBED / 8);
    for (size_t i = (size_t)blockIdx.x * blockDim.x + threadIdx.x;
         i < total; i += (size_t)gridDim.x * blockDim.x) {
        size_t row = i >> 7;
        int c8 = (int)(i & 127) * 8;
        const float4* s = (const float4*)(src + row * EMBED + c8);
        float4 v0 = s[0], v1 = s[1];
        float v[8] = {v0.x,v0.y,v0.z,v0.w,v1.x,v1.y,v1.z,v1.w};
        uint16_t hb[8], lb[8];
        #pragma unroll
        for (int j = 0; j < 8; j++) {
            __nv_bfloat16 h = __float2bfloat16(v[j]);
            __nv_bfloat16 l = __float2bfloat16(v[j] - __bfloat162float(h));
            hb[j] = __bfloat16_as_ushort(h);
            lb[j] = __bfloat16_as_ushort(l);
        }
        uint4 hp, lp;
        hp.x = hb[0] | ((uint32_t)hb[1]<<16); hp.y = hb[2] | ((uint32_t)hb[3]<<16);
        hp.z = hb[4] | ((uint32_t)hb[5]<<16); hp.w = hb[6] | ((uint32_t)hb[7]<<16);
        lp.x = lb[0] | ((uint32_t)lb[1]<<16); lp.y = lb[2] | ((uint32_t)lb[3]<<16);
        lp.z = lb[4] | ((uint32_t)lb[5]<<16); lp.w = lb[6] | ((uint32_t)lb[7]<<16);
        __nv_bfloat16* base = dst + row * KCAT + c8;
        *(uint4*)(base)             = hp;
        *(uint4*)(base + EMBED)     = wstyle ? hp : lp;
        *(uint4*)(base + 2*EMBED)   = wstyle ? lp : hp;
    }
}
__global__ __launch_bounds__(256) void split_x_kernel(const float* __restrict__ s)
{ split_body(s, g_Xc, MTOT, 0); }
__global__ __launch_bounds__(256) void split_wq_kernel(const float* __restrict__ s)
{ split_body(s, g_Wqc, QKV_N, 1); }
__global__ __launch_bounds__(256) void split_wo_kernel(const float* __restrict__ s)
{ split_body(s, g_Woc, EMBED, 1); }

// ---------------- HMMA GEMM core (proven round-6) ---------------------------
#define BKW 32
#define NKB (KCAT / BKW)
#define SSTR 40
#define BUFE (128 * SSTR)

__device__ __forceinline__ void hgemm_core(
    const uint4* __restrict__ A, const uint4* __restrict__ W,
    int m0, int n0, float acc[2][8][4])
{
    __shared__ __align__(16) __nv_bfloat16 sA[2][BUFE];
    __shared__ __align__(16) __nv_bfloat16 sW[2][BUFE];
    const int tid = threadIdx.x, lane = tid & 31, wid = tid >> 5;
    const int mw = wid & 3, nw = wid >> 2;
    const int lr = tid >> 2, lc = tid & 3;
    const size_t RS = KCAT / 8;

    #pragma unroll
    for (int i = 0; i < 2; i++)
        #pragma unroll
        for (int j = 0; j < 8; j++)
            #pragma unroll
            for (int k = 0; k < 4; k++) acc[i][j][k] = 0.f;

    uint4 pa0, pa1, pw0, pw1;
    pa0 = A[(size_t)(m0 + lr) * RS + lc];
    pa1 = A[(size_t)(m0 + 64 + lr) * RS + lc];
    pw0 = W[(size_t)(n0 + lr) * RS + lc];
    pw1 = W[(size_t)(n0 + 64 + lr) * RS + lc];
    *(uint4*)&sA[0][lr * SSTR + lc * 8]        = pa0;
    *(uint4*)&sA[0][(64 + lr) * SSTR + lc * 8] = pa1;
    *(uint4*)&sW[0][lr * SSTR + lc * 8]        = pw0;
    *(uint4*)&sW[0][(64 + lr) * SSTR + lc * 8] = pw1;
    __syncthreads();

    const uint32_t aB = smem_u32(&sA[0][0]);
    const uint32_t wB = smem_u32(&sW[0][0]);
    const uint32_t aOff = ((mw * 32 + (lane & 15)) * SSTR + ((lane >> 4) << 3)) * 2;
    const uint32_t wOff = ((nw * 64 + (((lane >> 4) & 1) << 3) + (lane & 7)) * SSTR
                          + (((lane >> 3) & 1) << 3)) * 2;

    for (int kb = 0; kb < NKB; kb++) {
        int cur = kb & 1;
        if (kb + 1 < NKB) {
            pa0 = A[(size_t)(m0 + lr) * RS + (kb + 1) * 4 + lc];
            pa1 = A[(size_t)(m0 + 64 + lr) * RS + (kb + 1) * 4 + lc];
            pw0 = W[(size_t)(n0 + lr) * RS + (kb + 1) * 4 + lc];
            pw1 = W[(size_t)(n0 + 64 + lr) * RS + (kb + 1) * 4 + lc];
        }
        uint32_t aCur = aB + cur * (BUFE * 2) + aOff;
        uint32_t wCur = wB + cur * (BUFE * 2) + wOff;
        #pragma unroll
        for (int kk = 0; kk < 2; kk++) {
            uint32_t af0[4], af1[4];
            ldm_x4(af0, aCur + kk * 32);
            ldm_x4(af1, aCur + (16 * SSTR) * 2 + kk * 32);
            #pragma unroll
            for (int g = 0; g < 4; g++) {
                uint32_t bf[4];
                ldm_x4(bf, wCur + (g * 16 * SSTR) * 2 + kk * 32);
                mma_bf16(acc[0][2*g+0], af0, bf[0], bf[1]);
                mma_bf16(acc[1][2*g+0], af1, bf[0], bf[1]);
                mma_bf16(acc[0][2*g+1], af0, bf[2], bf[3]);
                mma_bf16(acc[1][2*g+1], af1, bf[2], bf[3]);
            }
        }
        if (kb + 1 < NKB) {
            int nxt = cur ^ 1;
            *(uint4*)&sA[nxt][lr * SSTR + lc * 8]        = pa0;
            *(uint4*)&sA[nxt][(64 + lr) * SSTR + lc * 8] = pa1;
            *(uint4*)&sW[nxt][lr * SSTR + lc * 8]        = pw0;
            *(uint4*)&sW[nxt][(64 + lr) * SSTR + lc * 8] = pw1;
            __syncthreads();
        }
    }
}

// qkv: bias + head-split + bf16 hi/lo split -> g_{Q,K,V}{h,l}
__global__ __launch_bounds__(256, 2) void hq_qkv_kernel(const float* __restrict__ bias)
{
    float acc[2][8][4];
    const int m0 = blockIdx.y * 128, n0 = blockIdx.x * 128;
    hgemm_core((const uint4*)g_Xc, (const uint4*)g_Wqc, m0, n0, acc);

    const int lane = threadIdx.x & 31, wid = threadIdx.x >> 5;
    const int mw = wid & 3, nw = wid >> 2;
    #pragma unroll
    for (int mt = 0; mt < 2; mt++) {
        int mlo = m0 + mw * 32 + mt * 16 + (lane >> 2);
        int mhi = mlo + 8;
        int blo = mlo >> 11, slo = mlo & (SEQ - 1);
        int bhi = mhi >> 11, shi = mhi & (SEQ - 1);
        #pragma unroll
        for (int nt = 0; nt < 8; nt++) {
            int n = n0 + nw * 64 + nt * 8 + (lane & 3) * 2;
            int h = n / 192;
            int r = n - h * 192;
            int w = r >> 6;
            int d = r & 63;
            float2 bv = *(const float2*)&bias[n];
            float sc = (w == 0) ? 0.125f : 1.0f;
            __nv_bfloat16* Ah = (w == 0) ? g_Qh : (w == 1) ? g_Kh : g_Vh;
            __nv_bfloat16* Al = (w == 0) ? g_Ql : (w == 1) ? g_Kl : g_Vl;
            size_t i0 = (((size_t)(blo * NHEAD + h)) * SEQ + slo) * HD + d;
            size_t i1 = (((size_t)(bhi * NHEAD + h)) * SEQ + shi) * HD + d;
            uint32_t hi, lo;
            bsplit2(hi, lo, (acc[mt][nt][0] + bv.x) * sc, (acc[mt][nt][1] + bv.y) * sc);
            *(uint32_t*)&Ah[i0] = hi; *(uint32_t*)&Al[i0] = lo;
            bsplit2(hi, lo, (acc[mt][nt][2] + bv.x) * sc, (acc[mt][nt][3] + bv.y) * sc);
            *(uint32_t*)&Ah[i1] = hi; *(uint32_t*)&Al[i1] = lo;
        }
    }
}

// proj: bias + store to d_out
__global__ __launch_bounds__(256, 2) void hq_proj_kernel(const float* __restrict__ bias,
                                                         float* __restrict__ C)
{
    float acc[2][8][4];
    const int m0 = blockIdx.y * 128, n0 = blockIdx.x * 128;
    hgemm_core((const uint4*)g_AOc, (const uint4*)g_Woc, m0, n0, acc);

    const int lane = threadIdx.x & 31, wid = threadIdx.x >> 5;
    const int mw = wid & 3, nw = wid >> 2;
    #pragma unroll
    for (int mt = 0; mt < 2; mt++) {
        int mlo = m0 + mw * 32 + mt * 16 + (lane >> 2);
        int mhi = mlo + 8;
        #pragma unroll
        for (int nt = 0; nt < 8; nt++) {
            int n = n0 + nw * 64 + nt * 8 + (lane & 3) * 2;
            float2 bv = *(const float2*)&bias[n];
            *(float2*)&C[(size_t)mlo * EMBED + n] =
                make_float2(acc[mt][nt][0] + bv.x, acc[mt][nt][1] + bv.y);
            *(float2*)&C[(size_t)mhi * EMBED + n] =
                make_float2(acc[mt][nt][2] + bv.x, acc[mt][nt][3] + bv.y);
        }
    }
}

// ---------------------------------------------------------------------------
// HMMA flash attention. CTA = 128 q x one (b,h); 8 warps x 16 q-rows each.
// S = qh*kh + ql*kh + qh*kl ; P split ph+pl in regs ; O = ph*vh + pl*vh + ph*vl.
// smem: Kh,Kl [j][d] + Vh,Vl transposed [d][j], stride 72 (conflict-free ldm).
// ---------------------------------------------------------------------------
#define KSTR 72
#define KBUF (64 * KSTR)      // 4608 elements per buffer

__global__ __launch_bounds__(256) void attn_mma_kernel()
{
    __shared__ __align__(16) __nv_bfloat16 smb[4 * KBUF];  // Kh|Kl|VhT|VlT (36,864B)

    const int tid = threadIdx.x, lane = tid & 31, wid = tid >> 5;
    const int bh = blockIdx.y, q0 = blockIdx.x * 128;
    const size_t hdbase = (size_t)bh * SEQ * HD;

    // ---- load Q fragments (reuse smb as 128x72 staging) ----
    uint32_t qhf[4][4], qlf[4][4];
    {
        const uint32_t smbase = smem_u32(smb);
        const uint32_t aOff = smbase +
            ((wid * 16 + (lane & 15)) * KSTR + ((lane >> 4) << 3)) * 2;
        #pragma unroll
        for (int rep = 0; rep < 2; rep++) {
            const uint4* Qg = (const uint4*)((rep ? g_Ql : g_Qh) + hdbase + (size_t)q0 * HD);
            #pragma unroll
            for (int i = 0; i < 4; i++) {
                int idx = i * 256 + tid;
                int r = idx >> 3, c = idx & 7;
                *(uint4*)&smb[r * KSTR + c * 8] = Qg[r * 8 + c];
            }
            __syncthreads();
            #pragma unroll
            for (int kk = 0; kk < 4; kk++) {
                if (rep) ldm_x4(qlf[kk], aOff + kk * 32);
                else     ldm_x4(qhf[kk], aOff + kk * 32);
            }
            __syncthreads();
        }
    }

    const uint4* KgH = (const uint4*)(g_Kh + hdbase);
    const uint4* KgL = (const uint4*)(g_Kl + hdbase);
    const __nv_bfloat16* VgH = g_Vh + hdbase;
    const __nv_bfloat16* VgL = g_Vl + hdbase;

    // B-fragment ldmatrix base addresses (same pattern as proven hgemm wOff)
    const uint32_t smbase = smem_u32(smb);
    const uint32_t bOff = ((((lane >> 4) & 1) * 8 + (lane & 7)) * KSTR
                          + ((lane >> 3) & 1) * 8) * 2;
    const uint32_t khF = smbase + bOff;
    const uint32_t klF = khF + KBUF * 2;
    const uint32_t vhF = khF + 2 * KBUF * 2;
    const uint32_t vlF = khF + 3 * KBUF * 2;

    float m0r = -INFINITY, m1r = -INFINITY, l0r = 0.f, l1r = 0.f;
    float o[8][4];
    #pragma unroll
    for (int i = 0; i < 8; i++)
        #pragma unroll
        for (int j = 0; j < 4; j++) o[i][j] = 0.f;

    for (int t = 0; t < SEQ / 64; t++) {
        __syncthreads();
        {
            // K tiles: [j][d] rows
            int r = tid >> 2, c = tid & 3;
            const uint4* kr = KgH + (size_t)(t * 64 + r) * 8;
            *(uint4*)&smb[r * KSTR + c * 8]       = kr[c];
            *(uint4*)&smb[r * KSTR + (c + 4) * 8] = kr[c + 4];
            const uint4* kr2 = KgL + (size_t)(t * 64 + r) * 8;
            *(uint4*)&smb[KBUF + r * KSTR + c * 8]       = kr2[c];
            *(uint4*)&smb[KBUF + r * KSTR + (c + 4) * 8] = kr2[c + 4];
            // V tiles transposed: [d][j]
            int j = tid & 63, dg = tid >> 6, d0 = dg * 16;
            const __nv_bfloat16* vr = VgH + (size_t)(t * 64 + j) * HD + d0;
            const __nv_bfloat16* wr = VgL + (size_t)(t * 64 + j) * HD + d0;
            uint4 a0 = *(const uint4*)vr, a1 = *(const uint4*)(vr + 8);
            uint4 b0 = *(const uint4*)wr, b1 = *(const uint4*)(wr + 8);
            const uint16_t* ua = (const uint16_t*)&a0;
            const uint16_t* ub = (const uint16_t*)&b0;
            uint16_t* sh = (uint16_t*)&smb[2 * KBUF];
            uint16_t* sl = (uint16_t*)&smb[3 * KBUF];
            #pragma unroll
            for (int i = 0; i < 8; i++) {
                sh[(d0 + i) * KSTR + j] = ua[i];
                sl[(d0 + i) * KSTR + j] = ub[i];
            }
            const uint16_t* ua2 = (const uint16_t*)&a1;
            const uint16_t* ub2 = (const uint16_t*)&b1;
            #pragma unroll
            for (int i = 0; i < 8; i++) {
                sh[(d0 + 8 + i) * KSTR + j] = ua2[i];
                sl[(d0 + 8 + i) * KSTR + j] = ub2[i];
            }
        }
        __syncthreads();

        // ---- QK: S[16 x 64] ----
        float s[8][4];
        #pragma unroll
        for (int i = 0; i < 8; i++)
            #pragma unroll
            for (int j = 0; j < 4; j++) s[i][j] = 0.f;
        #pragma unroll
        for (int kk = 0; kk < 4; kk++) {
            #pragma unroll
            for (int g = 0; g < 4; g++) {
                uint32_t kf[4], lf[4];
                ldm_x4(kf, khF + g * (16 * KSTR * 2) + kk * 32);
                ldm_x4(lf, klF + g * (16 * KSTR * 2) + kk * 32);
                mma_bf16(s[2*g],   qhf[kk], kf[0], kf[1]);
                mma_bf16(s[2*g+1], qhf[kk], kf[2], kf[3]);
                mma_bf16(s[2*g],   qlf[kk], kf[0], kf[1]);
                mma_bf16(s[2*g+1], qlf[kk], kf[2], kf[3]);
                mma_bf16(s[2*g],   qhf[kk], lf[0], lf[1]);
                mma_bf16(s[2*g+1], qhf[kk], lf[2], lf[3]);
            }
        }

        // ---- online softmax (rows r=lane>>2 and r+8) ----
        float mx0 = s[0][0], mx1 = s[0][2];
        #pragma unroll
        for (int nt = 0; nt < 8; nt++) {
            mx0 = fmaxf(mx0, fmaxf(s[nt][0], s[nt][1]));
            mx1 = fmaxf(mx1, fmaxf(s[nt][2], s[nt][3]));
        }
        mx0 = fmaxf(mx0, __shfl_xor_sync(0xffffffffu, mx0, 1));
        mx0 = fmaxf(mx0, __shfl_xor_sync(0xffffffffu, mx0, 2));
        mx1 = fmaxf(mx1, __shfl_xor_sync(0xffffffffu, mx1, 1));
        mx1 = fmaxf(mx1, __shfl_xor_sync(0xffffffffu, mx1, 2));
        float mn0 = fmaxf(m0r, mx0), mn1 = fmaxf(m1r, mx1);
        float c0 = __expf(m0r - mn0), c1 = __expf(m1r - mn1);
        float sum0 = 0.f, sum1 = 0.f;
        #pragma unroll
        for (int nt = 0; nt < 8; nt++) {
            s[nt][0] = __expf(s[nt][0] - mn0); sum0 += s[nt][0];
            s[nt][1] = __expf(s[nt][1] - mn0); sum0 += s[nt][1];
            s[nt][2] = __expf(s[nt][2] - mn1); sum1 += s[nt][2];
            s[nt][3] = __expf(s[nt][3] - mn1); sum1 += s[nt][3];
        }
        sum0 += __shfl_xor_sync(0xffffffffu, sum0, 1);
        sum0 += __shfl_xor_sync(0xffffffffu, sum0, 2);
        sum1 += __shfl_xor_sync(0xffffffffu, sum1, 1);
        sum1 += __shfl_xor_sync(0xffffffffu, sum1, 2);
        l0r = l0r * c0 + sum0; l1r = l1r * c1 + sum1;
        m0r = mn0; m1r = mn1;
        #pragma unroll
        for (int nt = 0; nt < 8; nt++) {
            o[nt][0] *= c0; o[nt][1] *= c0;
            o[nt][2] *= c1; o[nt][3] *= c1;
        }

        // ---- PV: O += P * V (P C-frag -> A-frag register identity) ----
        #pragma unroll
        for (int js = 0; js < 4; js++) {
            uint32_t aph[4], apl[4];
            bsplit2(aph[0], apl[0], s[2*js][0],   s[2*js][1]);
            bsplit2(aph[1], apl[1], s[2*js][2],   s[2*js][3]);
            bsplit2(aph[2], apl[2], s[2*js+1][0], s[2*js+1][1]);
            bsplit2(aph[3], apl[3], s[2*js+1][2], s[2*js+1][3]);
            #pragma unroll
            for (int dg = 0; dg < 4; dg++) {
                uint32_t vf[4], wf[4];
                ldm_x4(vf, vhF + dg * (16 * KSTR * 2) + js * 32);
                ldm_x4(wf, vlF + dg * (16 * KSTR * 2) + js * 32);
                mma_bf16(o[2*dg],   aph, vf[0], vf[1]);
                mma_bf16(o[2*dg+1], aph, vf[2], vf[3]);
                mma_bf16(o[2*dg],   apl, vf[0], vf[1]);
                mma_bf16(o[2*dg+1], apl, vf[2], vf[3]);
                mma_bf16(o[2*dg],   aph, wf[0], wf[1]);
                mma_bf16(o[2*dg+1], aph, wf[2], wf[3]);
            }
        }
    }

    // ---- epilogue: O/l -> g_AOc split layout [hi | lo | hi] ----
    float inv0 = 1.f / l0r, inv1 = 1.f / l1r;
    int b = bh >> 4, h = bh & 15;
    int s0 = q0 + wid * 16 + (lane >> 2);
    size_t row0 = (size_t)(b * SEQ + s0) * KCAT;
    size_t row1 = row0 + (size_t)8 * KCAT;
    int colb = h * HD + (lane & 3) * 2;
    #pragma unroll
    for (int nt = 0; nt < 8; nt++) {
        int col = colb + nt * 8;
        uint32_t hi, lo;
        bsplit2(hi, lo, o[nt][0] * inv0, o[nt][1] * inv0);
        *(uint32_t*)&g_AOc[row0 + col]          = hi;
        *(uint32_t*)&g_AOc[row0 + EMBED + col]  = lo;
        *(uint32_t*)&g_AOc[row0 + 2*EMBED + col] = hi;
        bsplit2(hi, lo, o[nt][2] * inv1, o[nt][3] * inv1);
        *(uint32_t*)&g_AOc[row1 + col]          = hi;
        *(uint32_t*)&g_AOc[row1 + EMBED + col]  = lo;
        *(uint32_t*)&g_AOc[row1 + 2*EMBED + col] = hi;
    }
}

// ---------------------------------------------------------------------------
extern "C" void kernel_launch(void* const* d_in, const int* in_sizes, int n_in,
                              void* d_out, int out_size)
{
    const float* x     = (const float*)d_in[0];
    const float* qkv_w = (const float*)d_in[1];
    const float* qkv_b = (const float*)d_in[2];
    const float* out_w = (const float*)d_in[3];
    const float* out_b = (const float*)d_in[4];
    float* out = (float*)d_out;

    split_x_kernel <<<2048, 256>>>(x);
    split_wq_kernel<<<1536, 256>>>(qkv_w);
    split_wo_kernel<<<512,  256>>>(out_w);

    hq_qkv_kernel<<<dim3(QKV_N/128, MTOT/128), 256>>>(qkv_b);

    attn_mma_kernel<<<dim3(SEQ/128, BATCH*NHEAD), 256>>>();

    hq_proj_kernel<<<dim3(EMBED/128, MTOT/128), 256>>>(out_b, out);
}

// round 16
// speedup vs baseline: 4.8181x; 1.1882x over previous
#include <cuda_runtime.h>
#include <cuda_bf16.h>
#include <math.h>
#include <stdint.h>

#define EMBED 1024
#define NHEAD 16
#define HD    64
#define BATCH 4
#define SEQ   2048
#define MTOT  (BATCH*SEQ)     // 8192
#define QKV_N (3*EMBED)       // 3072
#define KCAT  (3*EMBED)       // split-concat K = 3072

// ---------------- scratch (device globals; no allocs allowed) ---------------
__device__ __align__(16) __nv_bfloat16 g_Qh[(size_t)BATCH*NHEAD*SEQ*HD]; // pre-scaled 1/8
__device__ __align__(16) __nv_bfloat16 g_Ql[(size_t)BATCH*NHEAD*SEQ*HD];
__device__ __align__(16) __nv_bfloat16 g_Kh[(size_t)BATCH*NHEAD*SEQ*HD];
__device__ __align__(16) __nv_bfloat16 g_Kl[(size_t)BATCH*NHEAD*SEQ*HD];
__device__ __align__(16) __nv_bfloat16 g_Vh[(size_t)BATCH*NHEAD*SEQ*HD];
__device__ __align__(16) __nv_bfloat16 g_Vl[(size_t)BATCH*NHEAD*SEQ*HD];
__device__ __align__(16) __nv_bfloat16 g_Xc [(size_t)MTOT*KCAT];    // x split-cat (A-style)
__device__ __align__(16) __nv_bfloat16 g_Wqc[(size_t)QKV_N*KCAT];   // qkv_w (W-style)
__device__ __align__(16) __nv_bfloat16 g_Woc[(size_t)EMBED*KCAT];   // out_w (W-style)
__device__ __align__(16) __nv_bfloat16 g_AOc[(size_t)MTOT*KCAT];    // attn out (A-style)

// ---------------- helpers ---------------------------------------------------
__device__ __forceinline__ uint32_t smem_u32(const void* p) {
    uint32_t a;
    asm("{ .reg .u64 t; cvta.to.shared.u64 t, %1; cvt.u32.u64 %0, t; }" : "=r"(a) : "l"(p));
    return a;
}
__device__ __forceinline__ void ldm_x4(uint32_t* r, uint32_t addr) {
    asm volatile("ldmatrix.sync.aligned.m8n8.x4.shared.b16 {%0,%1,%2,%3}, [%4];"
        : "=r"(r[0]), "=r"(r[1]), "=r"(r[2]), "=r"(r[3]) : "r"(addr));
}
__device__ __forceinline__ void ldm_x4_trans(uint32_t* r, uint32_t addr) {
    asm volatile("ldmatrix.sync.aligned.m8n8.x4.trans.shared.b16 {%0,%1,%2,%3}, [%4];"
        : "=r"(r[0]), "=r"(r[1]), "=r"(r[2]), "=r"(r[3]) : "r"(addr));
}
__device__ __forceinline__ void mma_bf16(float* d, const uint32_t* a,
                                         uint32_t b0, uint32_t b1) {
    asm volatile("mma.sync.aligned.m16n8k16.row.col.f32.bf16.bf16.f32 "
        "{%0,%1,%2,%3}, {%4,%5,%6,%7}, {%8,%9}, {%0,%1,%2,%3};"
        : "+f"(d[0]), "+f"(d[1]), "+f"(d[2]), "+f"(d[3])
        : "r"(a[0]), "r"(a[1]), "r"(a[2]), "r"(a[3]), "r"(b0), "r"(b1));
}
__device__ __forceinline__ void cpa16(uint32_t dst, const void* src) {
    asm volatile("cp.async.cg.shared.global [%0], [%1], 16;"
        :: "r"(dst), "l"(src) : "memory");
}
#define CPA_COMMIT() asm volatile("cp.async.commit_group;" ::: "memory")
#define CPA_WAIT(N)  asm volatile("cp.async.wait_group %0;" :: "n"(N) : "memory")

// split fp32 pair -> bf16x2 hi + bf16x2 lo (low half = first value)
__device__ __forceinline__ void bsplit2(uint32_t& hi, uint32_t& lo, float x, float y) {
    __nv_bfloat16 hx = __float2bfloat16(x), hy = __float2bfloat16(y);
    __nv_bfloat162 h2; h2.x = hx; h2.y = hy;
    hi = *(uint32_t*)&h2;
    __nv_bfloat162 l2 = __floats2bfloat162_rn(x - __bfloat162float(hx),
                                              y - __bfloat162float(hy));
    lo = *(uint32_t*)&l2;
}

// ---------------- split-bf16 conversion (GEMM operands) ---------------------
__device__ __forceinline__ void split_body(const float* __restrict__ src,
                                           __nv_bfloat16* __restrict__ dst,
                                           size_t nrows, int wstyle)
{
    size_t total = nrows * (EMBED / 8);
    for (size_t i = (size_t)blockIdx.x * blockDim.x + threadIdx.x;
         i < total; i += (size_t)gridDim.x * blockDim.x) {
        size_t row = i >> 7;
        int c8 = (int)(i & 127) * 8;
        const float4* s = (const float4*)(src + row * EMBED + c8);
        float4 v0 = s[0], v1 = s[1];
        float v[8] = {v0.x,v0.y,v0.z,v0.w,v1.x,v1.y,v1.z,v1.w};
        uint16_t hb[8], lb[8];
        #pragma unroll
        for (int j = 0; j < 8; j++) {
            __nv_bfloat16 h = __float2bfloat16(v[j]);
            __nv_bfloat16 l = __float2bfloat16(v[j] - __bfloat162float(h));
            hb[j] = __bfloat16_as_ushort(h);
            lb[j] = __bfloat16_as_ushort(l);
        }
        uint4 hp, lp;
        hp.x = hb[0] | ((uint32_t)hb[1]<<16); hp.y = hb[2] | ((uint32_t)hb[3]<<16);
        hp.z = hb[4] | ((uint32_t)hb[5]<<16); hp.w = hb[6] | ((uint32_t)hb[7]<<16);
        lp.x = lb[0] | ((uint32_t)lb[1]<<16); lp.y = lb[2] | ((uint32_t)lb[3]<<16);
        lp.z = lb[4] | ((uint32_t)lb[5]<<16); lp.w = lb[6] | ((uint32_t)lb[7]<<16);
        __nv_bfloat16* base = dst + row * KCAT + c8;
        *(uint4*)(base)             = hp;
        *(uint4*)(base + EMBED)     = wstyle ? hp : lp;
        *(uint4*)(base + 2*EMBED)   = wstyle ? lp : hp;
    }
}
__global__ __launch_bounds__(256) void split_x_kernel(const float* __restrict__ s)
{ split_body(s, g_Xc, MTOT, 0); }
__global__ __launch_bounds__(256) void split_wq_kernel(const float* __restrict__ s)
{ split_body(s, g_Wqc, QKV_N, 1); }
__global__ __launch_bounds__(256) void split_wo_kernel(const float* __restrict__ s)
{ split_body(s, g_Woc, EMBED, 1); }

// ---------------- HMMA GEMM core (proven round-6) ---------------------------
#define BKW 32
#define NKB (KCAT / BKW)
#define SSTR 40
#define BUFE (128 * SSTR)

__device__ __forceinline__ void hgemm_core(
    const uint4* __restrict__ A, const uint4* __restrict__ W,
    int m0, int n0, float acc[2][8][4])
{
    __shared__ __align__(16) __nv_bfloat16 sA[2][BUFE];
    __shared__ __align__(16) __nv_bfloat16 sW[2][BUFE];
    const int tid = threadIdx.x, lane = tid & 31, wid = tid >> 5;
    const int mw = wid & 3, nw = wid >> 2;
    const int lr = tid >> 2, lc = tid & 3;
    const size_t RS = KCAT / 8;

    #pragma unroll
    for (int i = 0; i < 2; i++)
        #pragma unroll
        for (int j = 0; j < 8; j++)
            #pragma unroll
            for (int k = 0; k < 4; k++) acc[i][j][k] = 0.f;

    uint4 pa0, pa1, pw0, pw1;
    pa0 = A[(size_t)(m0 + lr) * RS + lc];
    pa1 = A[(size_t)(m0 + 64 + lr) * RS + lc];
    pw0 = W[(size_t)(n0 + lr) * RS + lc];
    pw1 = W[(size_t)(n0 + 64 + lr) * RS + lc];
    *(uint4*)&sA[0][lr * SSTR + lc * 8]        = pa0;
    *(uint4*)&sA[0][(64 + lr) * SSTR + lc * 8] = pa1;
    *(uint4*)&sW[0][lr * SSTR + lc * 8]        = pw0;
    *(uint4*)&sW[0][(64 + lr) * SSTR + lc * 8] = pw1;
    __syncthreads();

    const uint32_t aB = smem_u32(&sA[0][0]);
    const uint32_t wB = smem_u32(&sW[0][0]);
    const uint32_t aOff = ((mw * 32 + (lane & 15)) * SSTR + ((lane >> 4) << 3)) * 2;
    const uint32_t wOff = ((nw * 64 + (((lane >> 4) & 1) << 3) + (lane & 7)) * SSTR
                          + (((lane >> 3) & 1) << 3)) * 2;

    for (int kb = 0; kb < NKB; kb++) {
        int cur = kb & 1;
        if (kb + 1 < NKB) {
            pa0 = A[(size_t)(m0 + lr) * RS + (kb + 1) * 4 + lc];
            pa1 = A[(size_t)(m0 + 64 + lr) * RS + (kb + 1) * 4 + lc];
            pw0 = W[(size_t)(n0 + lr) * RS + (kb + 1) * 4 + lc];
            pw1 = W[(size_t)(n0 + 64 + lr) * RS + (kb + 1) * 4 + lc];
        }
        uint32_t aCur = aB + cur * (BUFE * 2) + aOff;
        uint32_t wCur = wB + cur * (BUFE * 2) + wOff;
        #pragma unroll
        for (int kk = 0; kk < 2; kk++) {
            uint32_t af0[4], af1[4];
            ldm_x4(af0, aCur + kk * 32);
            ldm_x4(af1, aCur + (16 * SSTR) * 2 + kk * 32);
            #pragma unroll
            for (int g = 0; g < 4; g++) {
                uint32_t bf[4];
                ldm_x4(bf, wCur + (g * 16 * SSTR) * 2 + kk * 32);
                mma_bf16(acc[0][2*g+0], af0, bf[0], bf[1]);
                mma_bf16(acc[1][2*g+0], af1, bf[0], bf[1]);
                mma_bf16(acc[0][2*g+1], af0, bf[2], bf[3]);
                mma_bf16(acc[1][2*g+1], af1, bf[2], bf[3]);
            }
        }
        if (kb + 1 < NKB) {
            int nxt = cur ^ 1;
            *(uint4*)&sA[nxt][lr * SSTR + lc * 8]        = pa0;
            *(uint4*)&sA[nxt][(64 + lr) * SSTR + lc * 8] = pa1;
            *(uint4*)&sW[nxt][lr * SSTR + lc * 8]        = pw0;
            *(uint4*)&sW[nxt][(64 + lr) * SSTR + lc * 8] = pw1;
            __syncthreads();
        }
    }
}

// qkv: bias + head-split + bf16 hi/lo split -> g_{Q,K,V}{h,l}
__global__ __launch_bounds__(256, 2) void hq_qkv_kernel(const float* __restrict__ bias)
{
    float acc[2][8][4];
    const int m0 = blockIdx.y * 128, n0 = blockIdx.x * 128;
    hgemm_core((const uint4*)g_Xc, (const uint4*)g_Wqc, m0, n0, acc);

    const int lane = threadIdx.x & 31, wid = threadIdx.x >> 5;
    const int mw = wid & 3, nw = wid >> 2;
    #pragma unroll
    for (int mt = 0; mt < 2; mt++) {
        int mlo = m0 + mw * 32 + mt * 16 + (lane >> 2);
        int mhi = mlo + 8;
        int blo = mlo >> 11, slo = mlo & (SEQ - 1);
        int bhi = mhi >> 11, shi = mhi & (SEQ - 1);
        #pragma unroll
        for (int nt = 0; nt < 8; nt++) {
            int n = n0 + nw * 64 + nt * 8 + (lane & 3) * 2;
            int h = n / 192;
            int r = n - h * 192;
            int w = r >> 6;
            int d = r & 63;
            float2 bv = *(const float2*)&bias[n];
            float sc = (w == 0) ? 0.125f : 1.0f;
            __nv_bfloat16* Ah = (w == 0) ? g_Qh : (w == 1) ? g_Kh : g_Vh;
            __nv_bfloat16* Al = (w == 0) ? g_Ql : (w == 1) ? g_Kl : g_Vl;
            size_t i0 = (((size_t)(blo * NHEAD + h)) * SEQ + slo) * HD + d;
            size_t i1 = (((size_t)(bhi * NHEAD + h)) * SEQ + shi) * HD + d;
            uint32_t hi, lo;
            bsplit2(hi, lo, (acc[mt][nt][0] + bv.x) * sc, (acc[mt][nt][1] + bv.y) * sc);
            *(uint32_t*)&Ah[i0] = hi; *(uint32_t*)&Al[i0] = lo;
            bsplit2(hi, lo, (acc[mt][nt][2] + bv.x) * sc, (acc[mt][nt][3] + bv.y) * sc);
            *(uint32_t*)&Ah[i1] = hi; *(uint32_t*)&Al[i1] = lo;
        }
    }
}

// proj: bias + store to d_out
__global__ __launch_bounds__(256, 2) void hq_proj_kernel(const float* __restrict__ bias,
                                                         float* __restrict__ C)
{
    float acc[2][8][4];
    const int m0 = blockIdx.y * 128, n0 = blockIdx.x * 128;
    hgemm_core((const uint4*)g_AOc, (const uint4*)g_Woc, m0, n0, acc);

    const int lane = threadIdx.x & 31, wid = threadIdx.x >> 5;
    const int mw = wid & 3, nw = wid >> 2;
    #pragma unroll
    for (int mt = 0; mt < 2; mt++) {
        int mlo = m0 + mw * 32 + mt * 16 + (lane >> 2);
        int mhi = mlo + 8;
        #pragma unroll
        for (int nt = 0; nt < 8; nt++) {
            int n = n0 + nw * 64 + nt * 8 + (lane & 3) * 2;
            float2 bv = *(const float2*)&bias[n];
            *(float2*)&C[(size_t)mlo * EMBED + n] =
                make_float2(acc[mt][nt][0] + bv.x, acc[mt][nt][1] + bv.y);
            *(float2*)&C[(size_t)mhi * EMBED + n] =
                make_float2(acc[mt][nt][2] + bv.x, acc[mt][nt][3] + bv.y);
        }
    }
}

// ---------------------------------------------------------------------------
// HMMA flash attention, cp.async double-buffered.
// CTA = 128 q x one (b,h); 8 warps x 16 q-rows.
// K stored [j][d] (non-trans ldm); V stored [j][d] ROW-MAJOR, B frags via
// ldmatrix.x4.trans (no manual transpose). Tiles t+1 prefetched with
// cp.async.cg into the alternate buffer while tile t computes.
// ---------------------------------------------------------------------------
#define KSTR 72
#define KBUF (64 * KSTR)                 // 4608 elements per array
#define ATT_BUF_BYTES (4 * KBUF * 2)     // Kh|Kl|Vh|Vl = 36,864 B per buffer
#define ATT_SMEM (2 * ATT_BUF_BYTES)     // 73,728 B

__global__ __launch_bounds__(256) void attn_mma_kernel()
{
    extern __shared__ __align__(16) __nv_bfloat16 smb[];

    const int tid = threadIdx.x, lane = tid & 31, wid = tid >> 5;
    const int bh = blockIdx.y, q0 = blockIdx.x * 128;
    const size_t hdbase = (size_t)bh * SEQ * HD;
    const uint32_t sb = smem_u32(smb);

    // ---- load Q fragments (stage through smem region, then ldm) ----
    uint32_t qhf[4][4], qlf[4][4];
    {
        const uint32_t aOff = sb +
            ((wid * 16 + (lane & 15)) * KSTR + ((lane >> 4) << 3)) * 2;
        #pragma unroll
        for (int rep = 0; rep < 2; rep++) {
            const uint4* Qg = (const uint4*)((rep ? g_Ql : g_Qh) + hdbase + (size_t)q0 * HD);
            #pragma unroll
            for (int i = 0; i < 4; i++) {
                int idx = i * 256 + tid;
                int r = idx >> 3, c = idx & 7;
                *(uint4*)&smb[r * KSTR + c * 8] = Qg[r * 8 + c];
            }
            __syncthreads();
            #pragma unroll
            for (int kk = 0; kk < 4; kk++) {
                if (rep) ldm_x4(qlf[kk], aOff + kk * 32);
                else     ldm_x4(qhf[kk], aOff + kk * 32);
            }
            __syncthreads();
        }
    }

    const char* KgH = (const char*)(g_Kh + hdbase);
    const char* KgL = (const char*)(g_Kl + hdbase);
    const char* VgH = (const char*)(g_Vh + hdbase);
    const char* VgL = (const char*)(g_Vl + hdbase);

    // K B-frag pattern (rows j, non-trans — proven hgemm wOff form)
    const uint32_t bOff = ((((lane >> 4) & 1) * 8 + (lane & 7)) * KSTR
                          + ((lane >> 3) & 1) * 8) * 2;
    // V B-frag pattern (rows j, trans): j = lane&15, d-chunk = (lane>>4)*8
    const uint32_t vOffT = ((lane & 15) * KSTR + ((lane >> 4) & 1) * 8) * 2;

    // cp.async tile issue: 4 arrays x 64 rows x 128B; 8 ops per thread
    const int cpc = tid & 7;          // 16B chunk within 128B row
    const int cpr = tid >> 3;         // rows 0..31 (+32 second pass)
    auto issue_tile = [&](int t, int b) {
        uint32_t dbase = sb + (uint32_t)b * ATT_BUF_BYTES;
        size_t gbase = (size_t)(t * 64) * 128;   // byte offset of tile
        #pragma unroll
        for (int p = 0; p < 2; p++) {
            int r = cpr + p * 32;
            uint32_t doff = (uint32_t)(r * KSTR) * 2 + cpc * 16;
            size_t   goff = gbase + (size_t)r * 128 + cpc * 16;
            cpa16(dbase + doff,                KgH + goff);
            cpa16(dbase + KBUF*2 + doff,       KgL + goff);
            cpa16(dbase + 2*KBUF*2 + doff,     VgH + goff);
            cpa16(dbase + 3*KBUF*2 + doff,     VgL + goff);
        }
    };

    float m0r = -INFINITY, m1r = -INFINITY, l0r = 0.f, l1r = 0.f;
    float o[8][4];
    #pragma unroll
    for (int i = 0; i < 8; i++)
        #pragma unroll
        for (int j = 0; j < 4; j++) o[i][j] = 0.f;

    issue_tile(0, 0);
    CPA_COMMIT();

    const int NT = SEQ / 64;
    for (int t = 0; t < NT; t++) {
        int cur = t & 1;
        if (t + 1 < NT) {
            issue_tile(t + 1, cur ^ 1);
            CPA_COMMIT();
            CPA_WAIT(1);
        } else {
            CPA_WAIT(0);
        }
        __syncthreads();

        const uint32_t base = sb + (uint32_t)cur * ATT_BUF_BYTES;
        const uint32_t khA = base + bOff;
        const uint32_t klA = base + KBUF*2 + bOff;
        const uint32_t vhA = base + 2*KBUF*2 + vOffT;
        const uint32_t vlA = base + 3*KBUF*2 + vOffT;

        // ---- QK: S[16 x 64] = qh*kh + ql*kh + qh*kl ----
        float s[8][4];
        #pragma unroll
        for (int i = 0; i < 8; i++)
            #pragma unroll
            for (int j = 0; j < 4; j++) s[i][j] = 0.f;
        #pragma unroll
        for (int kk = 0; kk < 4; kk++) {
            #pragma unroll
            for (int g = 0; g < 4; g++) {
                uint32_t kf[4], lf[4];
                ldm_x4(kf, khA + g * (16 * KSTR * 2) + kk * 32);
                ldm_x4(lf, klA + g * (16 * KSTR * 2) + kk * 32);
                mma_bf16(s[2*g],   qhf[kk], kf[0], kf[1]);
                mma_bf16(s[2*g+1], qhf[kk], kf[2], kf[3]);
                mma_bf16(s[2*g],   qlf[kk], kf[0], kf[1]);
                mma_bf16(s[2*g+1], qlf[kk], kf[2], kf[3]);
                mma_bf16(s[2*g],   qhf[kk], lf[0], lf[1]);
                mma_bf16(s[2*g+1], qhf[kk], lf[2], lf[3]);
            }
        }

        // ---- online softmax (rows r=lane>>2 and r+8) ----
        float mx0 = s[0][0], mx1 = s[0][2];
        #pragma unroll
        for (int nt = 0; nt < 8; nt++) {
            mx0 = fmaxf(mx0, fmaxf(s[nt][0], s[nt][1]));
            mx1 = fmaxf(mx1, fmaxf(s[nt][2], s[nt][3]));
        }
        mx0 = fmaxf(mx0, __shfl_xor_sync(0xffffffffu, mx0, 1));
        mx0 = fmaxf(mx0, __shfl_xor_sync(0xffffffffu, mx0, 2));
        mx1 = fmaxf(mx1, __shfl_xor_sync(0xffffffffu, mx1, 1));
        mx1 = fmaxf(mx1, __shfl_xor_sync(0xffffffffu, mx1, 2));
        float mn0 = fmaxf(m0r, mx0), mn1 = fmaxf(m1r, mx1);
        float c0 = __expf(m0r - mn0), c1 = __expf(m1r - mn1);
        float sum0 = 0.f, sum1 = 0.f;
        #pragma unroll
        for (int nt = 0; nt < 8; nt++) {
            s[nt][0] = __expf(s[nt][0] - mn0); sum0 += s[nt][0];
            s[nt][1] = __expf(s[nt][1] - mn0); sum0 += s[nt][1];
            s[nt][2] = __expf(s[nt][2] - mn1); sum1 += s[nt][2];
            s[nt][3] = __expf(s[nt][3] - mn1); sum1 += s[nt][3];
        }
        sum0 += __shfl_xor_sync(0xffffffffu, sum0, 1);
        sum0 += __shfl_xor_sync(0xffffffffu, sum0, 2);
        sum1 += __shfl_xor_sync(0xffffffffu, sum1, 1);
        sum1 += __shfl_xor_sync(0xffffffffu, sum1, 2);
        l0r = l0r * c0 + sum0; l1r = l1r * c1 + sum1;
        m0r = mn0; m1r = mn1;
        #pragma unroll
        for (int nt = 0; nt < 8; nt++) {
            o[nt][0] *= c0; o[nt][1] *= c0;
            o[nt][2] *= c1; o[nt][3] *= c1;
        }

        // ---- PV: O += P * V;  V frags via ldmatrix.trans on row-major V ----
        #pragma unroll
        for (int js = 0; js < 4; js++) {
            uint32_t aph[4], apl[4];
            bsplit2(aph[0], apl[0], s[2*js][0],   s[2*js][1]);
            bsplit2(aph[1], apl[1], s[2*js][2],   s[2*js][3]);
            bsplit2(aph[2], apl[2], s[2*js+1][0], s[2*js+1][1]);
            bsplit2(aph[3], apl[3], s[2*js+1][2], s[2*js+1][3]);
            #pragma unroll
            for (int dg = 0; dg < 4; dg++) {
                uint32_t vf[4], wf[4];
                uint32_t toff = (uint32_t)(js * 16 * KSTR + dg * 16) * 2;
                ldm_x4_trans(vf, vhA + toff);
                ldm_x4_trans(wf, vlA + toff);
                mma_bf16(o[2*dg],   aph, vf[0], vf[1]);
                mma_bf16(o[2*dg+1], aph, vf[2], vf[3]);
                mma_bf16(o[2*dg],   apl, vf[0], vf[1]);
                mma_bf16(o[2*dg+1], apl, vf[2], vf[3]);
                mma_bf16(o[2*dg],   aph, wf[0], wf[1]);
                mma_bf16(o[2*dg+1], aph, wf[2], wf[3]);
            }
        }
        __syncthreads();   // next iteration's cp.async writes buf cur
    }

    // ---- epilogue: O/l -> g_AOc split layout [hi | lo | hi] ----
    float inv0 = 1.f / l0r, inv1 = 1.f / l1r;
    int b = bh >> 4, h = bh & 15;
    int s0 = q0 + wid * 16 + (lane >> 2);
    size_t row0 = (size_t)(b * SEQ + s0) * KCAT;
    size_t row1 = row0 + (size_t)8 * KCAT;
    int colb = h * HD + (lane & 3) * 2;
    #pragma unroll
    for (int nt = 0; nt < 8; nt++) {
        int col = colb + nt * 8;
        uint32_t hi, lo;
        bsplit2(hi, lo, o[nt][0] * inv0, o[nt][1] * inv0);
        *(uint32_t*)&g_AOc[row0 + col]          = hi;
        *(uint32_t*)&g_AOc[row0 + EMBED + col]  = lo;
        *(uint32_t*)&g_AOc[row0 + 2*EMBED + col] = hi;
        bsplit2(hi, lo, o[nt][2] * inv1, o[nt][3] * inv1);
        *(uint32_t*)&g_AOc[row1 + col]          = hi;
        *(uint32_t*)&g_AOc[row1 + EMBED + col]  = lo;
        *(uint32_t*)&g_AOc[row1 + 2*EMBED + col] = hi;
    }
}

// ---------------------------------------------------------------------------
extern "C" void kernel_launch(void* const* d_in, const int* in_sizes, int n_in,
                              void* d_out, int out_size)
{
    const float* x     = (const float*)d_in[0];
    const float* qkv_w = (const float*)d_in[1];
    const float* qkv_b = (const float*)d_in[2];
    const float* out_w = (const float*)d_in[3];
    const float* out_b = (const float*)d_in[4];
    float* out = (float*)d_out;

    cudaFuncSetAttribute(attn_mma_kernel,
                         cudaFuncAttributeMaxDynamicSharedMemorySize, ATT_SMEM);

    split_x_kernel <<<2048, 256>>>(x);
    split_wq_kernel<<<1536, 256>>>(qkv_w);
    split_wo_kernel<<<512,  256>>>(out_w);

    hq_qkv_kernel<<<dim3(QKV_N/128, MTOT/128), 256>>>(qkv_b);

    attn_mma_kernel<<<dim3(SEQ/128, BATCH*NHEAD), 256, ATT_SMEM>>>();

    hq_proj_kernel<<<dim3(EMBED/128, MTOT/128), 256>>>(out_b, out);
}